// round 14
// baseline (speedup 1.0000x reference)
#include <cuda_runtime.h>
#include <cuda_fp16.h>
#include <cuda_bf16.h>
#include <mma.h>

using namespace nvcuda;

// Problem constants (shapes fixed by the dataset)
#define MAXN 50000
#define MAXE 800000
#define F 128      // input features
#define H 4        // heads
#define C 32       // channels/head  (H*C == F)

// Scratch (device globals; no allocation allowed)
// g_xwh layout is HEAD-INTERLEAVED: g_xwh[n*128 + c*4 + h]  (c=0..31, h=0..3)
__device__ __half g_xwh[MAXN * F];
__device__ float g_ai[MAXN * H];        // att·xw first half  (source role)
__device__ float g_aj[MAXN * H];        // att·xw second half (dest role)
__device__ float g_p[MAXE * H];         // exp(leaky(alpha)) per edge (fp32)
__device__ float g_segsum[MAXN * H];    // softmax denominator per (row, h)

// ---------------------------------------------------------------------------
// vector atomic adds (sm_90+)
__device__ __forceinline__ void red_add_v4(float* p, float a, float b, float c, float d) {
    asm volatile("red.global.add.v4.f32 [%0], {%1, %2, %3, %4};"
                 :: "l"(p), "f"(a), "f"(b), "f"(c), "f"(d) : "memory");
}

// ---------------------------------------------------------------------------
// Tensor-core GEMM: xw = x @ W (fp16 HMMA, fp32 accum).
// Block = 32 rows x 128 cols, 8 warps, FULL K=128 staged in smem at once:
// all global loads issue up front (high MLP), ONE barrier, then 8 MMA steps
// per warp with no further syncs — collapses the latency chain that bound
// the old two-stage version (issue was 9-11%).
// Both smem tiles use 4-bank row-rotating padded strides (LD=136).
// Epilogue: head-interleaved fp16 xw store + attention half-dots ai/aj +
// segsum zero + out=bias init.
#define BM 32
#define LDS 136          // leading dim (halfs): 272B stride, bank-rotating
// smem layout (bytes):
//   sA: 32*136*2  = 8704   @ 0
//   sB: 128*136*2 = 34816  @ 8704   (ends 43520)
//   sC: 32*128*4  = 16384  @ 0      (epilogue reuse of sA/sB region)
//   s_att: 256 floats      @ 43520  -> total 44544 (< 48KB static limit)
#define SM_BYTES (43520 + 1024)

__global__ void k_gemm(const float* __restrict__ x, const float* __restrict__ w,
                       const float* __restrict__ att, const float* __restrict__ bias,
                       float* __restrict__ out, int N) {
    __shared__ __align__(16) char smbuf[SM_BYTES];
    __half* sA = (__half*)smbuf;                       // 32 x LDS
    __half* sB = (__half*)(smbuf + 32 * LDS * 2);      // 128 x LDS
    float*  sC = (float*)smbuf;                        // 32 x 128 (epilogue)
    float*  s_att = (float*)(smbuf + 43520);

    int tid = threadIdx.x;
    int row0 = blockIdx.x * BM;
    int warp = tid >> 5;
    int mt = warp & 1;            // m-tile (16 rows): 0..1
    int nb = (warp >> 1) * 32;    // n base (32 cols): 0,32,64,96

    s_att[tid] = att[tid];

    // ---- stage A: 32 rows x 128 cols fp32 -> fp16 (4 float4 per thread)
    {
        int arow = tid >> 3;              // 0..31
        int acol = (tid & 7) * 16;        // 0,16,...,112
        int grow = row0 + arow;
#pragma unroll
        for (int j = 0; j < 4; j++) {
            float4 v = make_float4(0.f, 0.f, 0.f, 0.f);
            if (grow < N) v = *(const float4*)&x[grow * F + acol + j * 4];
            __half2 h0 = __floats2half2_rn(v.x, v.y);
            __half2 h1 = __floats2half2_rn(v.z, v.w);
            *(__half2*)&sA[arow * LDS + acol + j * 4]     = h0;
            *(__half2*)&sA[arow * LDS + acol + j * 4 + 2] = h1;
        }
    }
    // ---- stage B: 128 rows x 128 cols fp32 -> fp16 (16 float4 per thread)
    {
        int brow = tid >> 1;              // 0..127
        int bcol = (tid & 1) * 64;        // 0 or 64
#pragma unroll
        for (int j = 0; j < 16; j++) {
            float4 v = *(const float4*)&w[brow * F + bcol + j * 4];
            __half2 h0 = __floats2half2_rn(v.x, v.y);
            __half2 h1 = __floats2half2_rn(v.z, v.w);
            *(__half2*)&sB[brow * LDS + bcol + j * 4]     = h0;
            *(__half2*)&sB[brow * LDS + bcol + j * 4 + 2] = h1;
        }
    }
    __syncthreads();

    // ---- MMA: 8 k-steps, no further syncs until epilogue
    wmma::fragment<wmma::accumulator, 16, 16, 16, float> acc[2];
    wmma::fill_fragment(acc[0], 0.0f);
    wmma::fill_fragment(acc[1], 0.0f);
#pragma unroll
    for (int kk = 0; kk < 8; kk++) {
        wmma::fragment<wmma::matrix_a, 16, 16, 16, __half, wmma::row_major> fa;
        wmma::load_matrix_sync(fa, &sA[mt * 16 * LDS + kk * 16], LDS);
#pragma unroll
        for (int nt = 0; nt < 2; nt++) {
            wmma::fragment<wmma::matrix_b, 16, 16, 16, __half, wmma::row_major> fb;
            wmma::load_matrix_sync(fb, &sB[kk * 16 * LDS + nb + nt * 16], LDS);
            wmma::mma_sync(acc[nt], fa, fb, acc[nt]);
        }
    }
    __syncthreads();   // before sC overwrites sA/sB

#pragma unroll
    for (int nt = 0; nt < 2; nt++)
        wmma::store_matrix_sync(&sC[mt * 16 * F + nb + nt * 16], acc[nt], F, wmma::mem_row_major);
    __syncthreads();

    // ---- epilogue: thread t -> (local row = t>>3, channel-eighth q = t&7)
    {
        int lrow = tid >> 3;
        int q = tid & 7;                  // 4 channels (all heads) each
        int grow = row0 + lrow;
        float s1[H], s2[H];
        __half buf[16];
#pragma unroll
        for (int h = 0; h < H; h++) { s1[h] = 0.f; s2[h] = 0.f; }
#pragma unroll
        for (int h = 0; h < H; h++) {
            const float* cr = &sC[lrow * F + h * C + q * 4];
            const float* a1 = &s_att[h * 2 * C + q * 4];
            const float* a2 = a1 + C;
#pragma unroll
            for (int j = 0; j < 4; j++) {
                float v = cr[j];
                s1[h] += v * a1[j];
                s2[h] += v * a2[j];
                buf[j * 4 + h] = __float2half_rn(v);   // interleaved [c][h]
            }
        }
        // butterfly over the 8 q-lanes (same warp: 4 rows x 8 lanes)
#pragma unroll
        for (int h = 0; h < H; h++) {
            s1[h] += __shfl_xor_sync(0xffffffffu, s1[h], 1);
            s1[h] += __shfl_xor_sync(0xffffffffu, s1[h], 2);
            s1[h] += __shfl_xor_sync(0xffffffffu, s1[h], 4);
            s2[h] += __shfl_xor_sync(0xffffffffu, s2[h], 1);
            s2[h] += __shfl_xor_sync(0xffffffffu, s2[h], 2);
            s2[h] += __shfl_xor_sync(0xffffffffu, s2[h], 4);
        }
        if (grow < N) {
            // 32B contiguous fp16 store (channels q*4..q*4+3, all heads)
            *(uint4*)&g_xwh[grow * F + q * 16]     = *(uint4*)&buf[0];
            *(uint4*)&g_xwh[grow * F + q * 16 + 8] = *(uint4*)&buf[8];
            if (q < 4) {
                g_ai[grow * H + q] = s1[q];
                g_aj[grow * H + q] = s2[q];
                g_segsum[grow * H + q] = 0.0f;
            }
            // out = bias  (channels q*4 .. q*4+3)
            *(float4*)&out[grow * C + q * 4] = *(const float4*)&bias[q * 4];
        }
    }
}

// ---------------------------------------------------------------------------
// fast exp on the FMA/ALU pipes (no MUFU): exp(x) = 2^(x*log2e),
// 2^t = 2^floor(t) * poly(frac(t)), exponent added via integer bit trick.
__device__ __forceinline__ float fast_exp(float x) {
    float t = x * 1.4426950408889634f;
    t = fminf(fmaxf(t, -80.0f), 80.0f);
    float fi = floorf(t);
    float f = t - fi;
    float p = 1.3534581508e-2f;
    p = fmaf(p, f, 5.2011464331e-2f);
    p = fmaf(p, f, 2.4144275732e-1f);
    p = fmaf(p, f, 6.9300613463e-1f);
    p = fmaf(p, f, 9.9999989038e-1f);
    return __int_as_float(__float_as_int(p) + ((int)fi << 23));
}

__device__ __forceinline__ float leaky_exp(float a) {
    a = (a >= 0.f) ? a : 0.2f * a;
    return fast_exp(a);
}

// ---------------------------------------------------------------------------
// per-edge: p = exp(leaky(a_i[row] + a_j[col])); segsum[row] += p (one v4 red)
// (softmax max-shift skipped: shift-invariant, |alpha| small -> no overflow)
__global__ void k_edge1(const int* __restrict__ ei, int E) {
    int e = blockIdx.x * blockDim.x + threadIdx.x;
    if (e >= E) return;
    int r = ei[e];
    int c = ei[E + e];
    float4 ai = *(const float4*)&g_ai[r * H];
    float4 aj = *(const float4*)&g_aj[c * H];
    float4 p;
    p.x = leaky_exp(ai.x + aj.x);
    p.y = leaky_exp(ai.y + aj.y);
    p.z = leaky_exp(ai.z + aj.z);
    p.w = leaky_exp(ai.w + aj.w);
    *(float4*)&g_p[e * H] = p;
    red_add_v4(&g_segsum[r * H], p.x, p.y, p.z, p.w);
}

// ---------------------------------------------------------------------------
// aggregation: 8 lanes per edge, 4 edges per warp. The softmax reciprocal is
// computed inline from the gathered segsum (MUFU.RCP via __fdividef).
// Lane l covers output channels 4l..4l+3: loads 32B, folds heads, one red.v4.
__global__ void k_edge2(const int* __restrict__ ei, float* __restrict__ out, int E) {
    int gt = blockIdx.x * blockDim.x + threadIdx.x;
    int e = gt >> 3;
    if (e >= E) return;
    int l = gt & 7;

    int r = __ldg(&ei[e]);
    int c = __ldg(&ei[E + e]);

    float4 p = *(const float4*)&g_p[e * H];
    float4 s = *(const float4*)&g_segsum[r * H];
    float w0 = p.x * __fdividef(0.25f, s.x + 1e-16f);
    float w1 = p.y * __fdividef(0.25f, s.y + 1e-16f);
    float w2 = p.z * __fdividef(0.25f, s.z + 1e-16f);
    float w3 = p.w * __fdividef(0.25f, s.w + 1e-16f);

    // channels 4l..4l+3 -> halfs [16l .. 16l+15] (32B contiguous)
    const __half* xr = &g_xwh[r * F + l * 16];
    uint4 ua = *(const uint4*)&xr[0];   // c0:{h0..h3}, c1:{h0..h3}
    uint4 ub = *(const uint4*)&xr[8];   // c2:{h0..h3}, c3:{h0..h3}

    float2 c0a = __half22float2(*reinterpret_cast<__half2*>(&ua.x));
    float2 c0b = __half22float2(*reinterpret_cast<__half2*>(&ua.y));
    float2 c1a = __half22float2(*reinterpret_cast<__half2*>(&ua.z));
    float2 c1b = __half22float2(*reinterpret_cast<__half2*>(&ua.w));
    float2 c2a = __half22float2(*reinterpret_cast<__half2*>(&ub.x));
    float2 c2b = __half22float2(*reinterpret_cast<__half2*>(&ub.y));
    float2 c3a = __half22float2(*reinterpret_cast<__half2*>(&ub.z));
    float2 c3b = __half22float2(*reinterpret_cast<__half2*>(&ub.w));

    float m0 = w0 * c0a.x + w1 * c0a.y + w2 * c0b.x + w3 * c0b.y;
    float m1 = w0 * c1a.x + w1 * c1a.y + w2 * c1b.x + w3 * c1b.y;
    float m2 = w0 * c2a.x + w1 * c2a.y + w2 * c2b.x + w3 * c2b.y;
    float m3 = w0 * c3a.x + w1 * c3a.y + w2 * c3b.x + w3 * c3b.y;

    red_add_v4(&out[c * C + l * 4], m0, m1, m2, m3);
}

// ---------------------------------------------------------------------------
extern "C" void kernel_launch(void* const* d_in, const int* in_sizes, int n_in,
                              void* d_out, int out_size) {
    const float* x    = (const float*)d_in[0];
    const int*   ei   = (const int*)d_in[1];
    const float* w    = (const float*)d_in[2];
    const float* att  = (const float*)d_in[3];
    const float* bias = (const float*)d_in[4];
    float* out = (float*)d_out;

    int N = in_sizes[0] / F;
    int E = in_sizes[1] / 2;

    k_gemm<<<(N + BM - 1) / BM, 256>>>(x, w, att, bias, out, N);
    k_edge1<<<(E + 255) / 256, 256>>>(ei, E);
    k_edge2<<<(E * 8 + 255) / 256, 256>>>(ei, out, E);
}

// round 15
// speedup vs baseline: 1.1602x; 1.1602x over previous
#include <cuda_runtime.h>
#include <cuda_fp16.h>
#include <cuda_bf16.h>
#include <mma.h>

using namespace nvcuda;

// Problem constants (shapes fixed by the dataset)
#define MAXN 50000
#define MAXE 800000
#define F 128      // input features
#define H 4        // heads
#define C 32       // channels/head  (H*C == F)

// Scratch (device globals; no allocation allowed)
// g_xwh layout is HEAD-INTERLEAVED: g_xwh[n*128 + c*4 + h]  (c=0..31, h=0..3)
__device__ __half g_xwh[MAXN * F];
__device__ float g_ai[MAXN * H];        // att·xw first half  (source role)
__device__ float g_aj[MAXN * H];        // att·xw second half (dest role)
__device__ float g_p[MAXE * H];         // exp(leaky(alpha)) per edge (fp32)
__device__ float g_segsum[MAXN * H];    // softmax denominator per (row, h)

// ---------------------------------------------------------------------------
// vector atomic adds (sm_90+)
__device__ __forceinline__ void red_add_v4(float* p, float a, float b, float c, float d) {
    asm volatile("red.global.add.v4.f32 [%0], {%1, %2, %3, %4};"
                 :: "l"(p), "f"(a), "f"(b), "f"(c), "f"(d) : "memory");
}

// ---------------------------------------------------------------------------
// Tensor-core GEMM: xw = x @ W (fp16 HMMA, fp32 accum).
// Block = 64 rows x 128 cols, 8 warps arranged 2(m-groups) x 4(n-groups):
// each warp owns 2 m-tiles x 2 n-tiles (acc[2][2]). Per-kk fragment loads
// drop from 40 (old 4x2 layout) to 32 — 20% less LDSM traffic through the
// L1 pipe that binds this kernel. Both smem tiles use 4-bank row-rotating
// padded strides (LDA=72, LDB=136) so load_matrix_sync is conflict-free.
// Epilogue: head-interleaved fp16 xw store + attention half-dots ai/aj +
// segsum zero + out=bias init.
#define BM 64
#define LDA 72           // sA leading dim (halfs): 144B stride, bank-rotating
#define LDB 136          // sB leading dim (halfs): 272B stride, bank-rotating
#define SM_BYTES (32768 + 1024)

__global__ void k_gemm(const float* __restrict__ x, const float* __restrict__ w,
                       const float* __restrict__ att, const float* __restrict__ bias,
                       float* __restrict__ out, int N) {
    __shared__ __align__(16) char smbuf[SM_BYTES];
    __half* sA = (__half*)smbuf;                       // 64*72*2  = 9216 B
    __half* sB = (__half*)(smbuf + 64 * LDA * 2);      // 64*136*2 = 17408 B (ends 26624)
    float*  sC = (float*)smbuf;                        // 64*128*4 = 32768 B (epilogue reuse)
    float*  s_att = (float*)(smbuf + 32768);

    int tid = threadIdx.x;
    int row0 = blockIdx.x * BM;
    int warp = tid >> 5;
    int wm = warp & 1;            // m-group: rows wm*32 .. wm*32+31 (2 m-tiles)
    int wn = warp >> 1;           // n-group: cols wn*32 .. wn*32+31 (2 n-tiles)

    s_att[tid] = att[tid];

    wmma::fragment<wmma::accumulator, 16, 16, 16, float> acc[2][2];
#pragma unroll
    for (int mi = 0; mi < 2; mi++)
#pragma unroll
        for (int ni = 0; ni < 2; ni++) wmma::fill_fragment(acc[mi][ni], 0.0f);

    int arow = tid >> 2;          // 0..63
    int aq   = (tid & 3) * 16;    // k-offset within stage
    int brow = tid >> 2;          // 0..63 (k index within stage)
    int bs   = (tid & 3) * 32;    // col segment

#pragma unroll
    for (int k0 = 0; k0 < F; k0 += 64) {
        {
            int grow = row0 + arow;
#pragma unroll
            for (int j = 0; j < 4; j++) {
                float4 v = make_float4(0.f, 0.f, 0.f, 0.f);
                if (grow < N) v = *(const float4*)&x[grow * F + k0 + aq + j * 4];
                __half2 h0 = __floats2half2_rn(v.x, v.y);
                __half2 h1 = __floats2half2_rn(v.z, v.w);
                *(__half2*)&sA[arow * LDA + aq + j * 4]     = h0;
                *(__half2*)&sA[arow * LDA + aq + j * 4 + 2] = h1;
            }
        }
        {
#pragma unroll
            for (int j = 0; j < 8; j++) {
                float4 v = *(const float4*)&w[(k0 + brow) * F + bs + j * 4];
                __half2 h0 = __floats2half2_rn(v.x, v.y);
                __half2 h1 = __floats2half2_rn(v.z, v.w);
                *(__half2*)&sB[brow * LDB + bs + j * 4]     = h0;
                *(__half2*)&sB[brow * LDB + bs + j * 4 + 2] = h1;
            }
        }
        __syncthreads();

#pragma unroll
        for (int kk = 0; kk < 4; kk++) {
            wmma::fragment<wmma::matrix_a, 16, 16, 16, __half, wmma::row_major> fa[2];
            wmma::fragment<wmma::matrix_b, 16, 16, 16, __half, wmma::row_major> fb[2];
#pragma unroll
            for (int mi = 0; mi < 2; mi++)
                wmma::load_matrix_sync(fa[mi], &sA[(wm * 32 + mi * 16) * LDA + kk * 16], LDA);
#pragma unroll
            for (int ni = 0; ni < 2; ni++)
                wmma::load_matrix_sync(fb[ni], &sB[kk * 16 * LDB + wn * 32 + ni * 16], LDB);
#pragma unroll
            for (int mi = 0; mi < 2; mi++)
#pragma unroll
                for (int ni = 0; ni < 2; ni++)
                    wmma::mma_sync(acc[mi][ni], fa[mi], fb[ni], acc[mi][ni]);
        }
        __syncthreads();
    }

#pragma unroll
    for (int mi = 0; mi < 2; mi++)
#pragma unroll
        for (int ni = 0; ni < 2; ni++)
            wmma::store_matrix_sync(&sC[(wm * 32 + mi * 16) * F + wn * 32 + ni * 16],
                                    acc[mi][ni], F, wmma::mem_row_major);
    __syncthreads();

    // epilogue: thread t -> (local row = t>>2, channel quarter q = t&3)
    {
        int lrow = tid >> 2;
        int q = tid & 3;
        int grow = row0 + lrow;
        float s1[H], s2[H];
        __half buf[32];
#pragma unroll
        for (int h = 0; h < H; h++) { s1[h] = 0.f; s2[h] = 0.f; }
#pragma unroll
        for (int h = 0; h < H; h++) {
            const float* cr = &sC[lrow * F + h * C + q * 8];
            const float* a1 = &s_att[h * 2 * C + q * 8];
            const float* a2 = a1 + C;
#pragma unroll
            for (int j = 0; j < 8; j++) {
                float v = cr[j];
                s1[h] += v * a1[j];
                s2[h] += v * a2[j];
                buf[j * 4 + h] = __float2half_rn(v);   // interleaved [c][h]
            }
        }
        // butterfly over the 4 q-lanes: elementwise sum per head
#pragma unroll
        for (int h = 0; h < H; h++) {
            s1[h] += __shfl_xor_sync(0xffffffffu, s1[h], 1);
            s1[h] += __shfl_xor_sync(0xffffffffu, s1[h], 2);
            s2[h] += __shfl_xor_sync(0xffffffffu, s2[h], 1);
            s2[h] += __shfl_xor_sync(0xffffffffu, s2[h], 2);
        }
        if (grow < N) {
            // 64B contiguous fp16 store (channels q*8..q*8+7, all heads)
            *(uint4*)&g_xwh[grow * F + q * 32]      = *(uint4*)&buf[0];
            *(uint4*)&g_xwh[grow * F + q * 32 + 8]  = *(uint4*)&buf[8];
            *(uint4*)&g_xwh[grow * F + q * 32 + 16] = *(uint4*)&buf[16];
            *(uint4*)&g_xwh[grow * F + q * 32 + 24] = *(uint4*)&buf[24];
            g_ai[grow * H + q] = s1[q];
            g_aj[grow * H + q] = s2[q];
            g_segsum[grow * H + q] = 0.0f;
            // out = bias  (channels q*8 .. q*8+7)
            float4 b0 = *(const float4*)&bias[q * 8];
            float4 b1 = *(const float4*)&bias[q * 8 + 4];
            *(float4*)&out[grow * C + q * 8]     = b0;
            *(float4*)&out[grow * C + q * 8 + 4] = b1;
        }
    }
}

// ---------------------------------------------------------------------------
// fast exp on the FMA/ALU pipes (no MUFU): exp(x) = 2^(x*log2e),
// 2^t = 2^floor(t) * poly(frac(t)), exponent added via integer bit trick.
__device__ __forceinline__ float fast_exp(float x) {
    float t = x * 1.4426950408889634f;
    t = fminf(fmaxf(t, -80.0f), 80.0f);
    float fi = floorf(t);
    float f = t - fi;
    float p = 1.3534581508e-2f;
    p = fmaf(p, f, 5.2011464331e-2f);
    p = fmaf(p, f, 2.4144275732e-1f);
    p = fmaf(p, f, 6.9300613463e-1f);
    p = fmaf(p, f, 9.9999989038e-1f);
    return __int_as_float(__float_as_int(p) + ((int)fi << 23));
}

__device__ __forceinline__ float leaky_exp(float a) {
    a = (a >= 0.f) ? a : 0.2f * a;
    return fast_exp(a);
}

// ---------------------------------------------------------------------------
// per-edge: p = exp(leaky(a_i[row] + a_j[col])); segsum[row] += p (one v4 red)
// (softmax max-shift skipped: shift-invariant, |alpha| small -> no overflow)
__global__ void k_edge1(const int* __restrict__ ei, int E) {
    int e = blockIdx.x * blockDim.x + threadIdx.x;
    if (e >= E) return;
    int r = ei[e];
    int c = ei[E + e];
    float4 ai = *(const float4*)&g_ai[r * H];
    float4 aj = *(const float4*)&g_aj[c * H];
    float4 p;
    p.x = leaky_exp(ai.x + aj.x);
    p.y = leaky_exp(ai.y + aj.y);
    p.z = leaky_exp(ai.z + aj.z);
    p.w = leaky_exp(ai.w + aj.w);
    *(float4*)&g_p[e * H] = p;
    red_add_v4(&g_segsum[r * H], p.x, p.y, p.z, p.w);
}

// ---------------------------------------------------------------------------
// aggregation: 8 lanes per edge, 4 edges per warp. The softmax reciprocal is
// computed inline from the gathered segsum (MUFU.RCP via __fdividef).
// Lane l covers output channels 4l..4l+3: loads 32B, folds heads, one red.v4.
__global__ void k_edge2(const int* __restrict__ ei, float* __restrict__ out, int E) {
    int gt = blockIdx.x * blockDim.x + threadIdx.x;
    int e = gt >> 3;
    if (e >= E) return;
    int l = gt & 7;

    int r = __ldg(&ei[e]);
    int c = __ldg(&ei[E + e]);

    float4 p = *(const float4*)&g_p[e * H];
    float4 s = *(const float4*)&g_segsum[r * H];
    float w0 = p.x * __fdividef(0.25f, s.x + 1e-16f);
    float w1 = p.y * __fdividef(0.25f, s.y + 1e-16f);
    float w2 = p.z * __fdividef(0.25f, s.z + 1e-16f);
    float w3 = p.w * __fdividef(0.25f, s.w + 1e-16f);

    // channels 4l..4l+3 -> halfs [16l .. 16l+15] (32B contiguous)
    const __half* xr = &g_xwh[r * F + l * 16];
    uint4 ua = *(const uint4*)&xr[0];   // c0:{h0..h3}, c1:{h0..h3}
    uint4 ub = *(const uint4*)&xr[8];   // c2:{h0..h3}, c3:{h0..h3}

    float2 c0a = __half22float2(*reinterpret_cast<__half2*>(&ua.x));
    float2 c0b = __half22float2(*reinterpret_cast<__half2*>(&ua.y));
    float2 c1a = __half22float2(*reinterpret_cast<__half2*>(&ua.z));
    float2 c1b = __half22float2(*reinterpret_cast<__half2*>(&ua.w));
    float2 c2a = __half22float2(*reinterpret_cast<__half2*>(&ub.x));
    float2 c2b = __half22float2(*reinterpret_cast<__half2*>(&ub.y));
    float2 c3a = __half22float2(*reinterpret_cast<__half2*>(&ub.z));
    float2 c3b = __half22float2(*reinterpret_cast<__half2*>(&ub.w));

    float m0 = w0 * c0a.x + w1 * c0a.y + w2 * c0b.x + w3 * c0b.y;
    float m1 = w0 * c1a.x + w1 * c1a.y + w2 * c1b.x + w3 * c1b.y;
    float m2 = w0 * c2a.x + w1 * c2a.y + w2 * c2b.x + w3 * c2b.y;
    float m3 = w0 * c3a.x + w1 * c3a.y + w2 * c3b.x + w3 * c3b.y;

    red_add_v4(&out[c * C + l * 4], m0, m1, m2, m3);
}

// ---------------------------------------------------------------------------
extern "C" void kernel_launch(void* const* d_in, const int* in_sizes, int n_in,
                              void* d_out, int out_size) {
    const float* x    = (const float*)d_in[0];
    const int*   ei   = (const int*)d_in[1];
    const float* w    = (const float*)d_in[2];
    const float* att  = (const float*)d_in[3];
    const float* bias = (const float*)d_in[4];
    float* out = (float*)d_out;

    int N = in_sizes[0] / F;
    int E = in_sizes[1] / 2;

    k_gemm<<<(N + BM - 1) / BM, 256>>>(x, w, att, bias, out, N);
    k_edge1<<<(E + 255) / 256, 256>>>(ei, E);
    k_edge2<<<(E * 8 + 255) / 256, 256>>>(ei, out, E);
}

// round 17
// speedup vs baseline: 1.1979x; 1.0325x over previous
#include <cuda_runtime.h>
#include <cuda_fp16.h>
#include <cuda_bf16.h>
#include <mma.h>

using namespace nvcuda;

// Problem constants (shapes fixed by the dataset)
#define MAXN 50000
#define MAXE 800000
#define F 128      // input features
#define H 4        // heads
#define C 32       // channels/head  (H*C == F)

// Scratch (device globals; no allocation allowed)
// g_xwh layout is HEAD-INTERLEAVED: g_xwh[n*128 + c*4 + h]  (c=0..31, h=0..3)
__device__ __half g_xwh[MAXN * F];
__device__ float g_ai[MAXN * H];        // att·xw first half  (source role)
__device__ float g_aj[MAXN * H];        // att·xw second half (dest role)
__device__ float g_p[MAXE * H];         // exp(leaky(alpha)) per edge (fp32)
__device__ float g_segsum[MAXN * H];    // softmax denominator per (row, h)

// ---------------------------------------------------------------------------
// vector atomic adds (sm_90+)
__device__ __forceinline__ void red_add_v4(float* p, float a, float b, float c, float d) {
    asm volatile("red.global.add.v4.f32 [%0], {%1, %2, %3, %4};"
                 :: "l"(p), "f"(a), "f"(b), "f"(c), "f"(d) : "memory");
}

// ---------------------------------------------------------------------------
// Tensor-core GEMM: xw = x @ W (fp16 HMMA, fp32 accum). R15-validated version:
// Block = 64 rows x 128 cols, 8 warps arranged 2(m) x 4(n), acc[2][2]/warp.
// Conflict-free padded smem (LDA=72, LDB=136). Fused epilogue: interleaved
// fp16 xw store + attention half-dots + segsum zero + out=bias init.
#define BM 64
#define LDA 72
#define LDB 136
#define SM_BYTES (32768 + 1024)

__global__ void k_gemm(const float* __restrict__ x, const float* __restrict__ w,
                       const float* __restrict__ att, const float* __restrict__ bias,
                       float* __restrict__ out, int N) {
    __shared__ __align__(16) char smbuf[SM_BYTES];
    __half* sA = (__half*)smbuf;                       // 64*72*2  = 9216 B
    __half* sB = (__half*)(smbuf + 64 * LDA * 2);      // 64*136*2 = 17408 B
    float*  sC = (float*)smbuf;                        // 64*128*4 = 32768 B (epilogue reuse)
    float*  s_att = (float*)(smbuf + 32768);

    int tid = threadIdx.x;
    int row0 = blockIdx.x * BM;
    int warp = tid >> 5;
    int wm = warp & 1;            // m-group: rows wm*32.. (2 m-tiles)
    int wn = warp >> 1;           // n-group: cols wn*32.. (2 n-tiles)

    s_att[tid] = att[tid];

    wmma::fragment<wmma::accumulator, 16, 16, 16, float> acc[2][2];
#pragma unroll
    for (int mi = 0; mi < 2; mi++)
#pragma unroll
        for (int ni = 0; ni < 2; ni++) wmma::fill_fragment(acc[mi][ni], 0.0f);

    int arow = tid >> 2;          // 0..63
    int aq   = (tid & 3) * 16;
    int brow = tid >> 2;          // 0..63
    int bs   = (tid & 3) * 32;

#pragma unroll
    for (int k0 = 0; k0 < F; k0 += 64) {
        {
            int grow = row0 + arow;
#pragma unroll
            for (int j = 0; j < 4; j++) {
                float4 v = make_float4(0.f, 0.f, 0.f, 0.f);
                if (grow < N) v = *(const float4*)&x[grow * F + k0 + aq + j * 4];
                __half2 h0 = __floats2half2_rn(v.x, v.y);
                __half2 h1 = __floats2half2_rn(v.z, v.w);
                *(__half2*)&sA[arow * LDA + aq + j * 4]     = h0;
                *(__half2*)&sA[arow * LDA + aq + j * 4 + 2] = h1;
            }
        }
        {
#pragma unroll
            for (int j = 0; j < 8; j++) {
                float4 v = *(const float4*)&w[(k0 + brow) * F + bs + j * 4];
                __half2 h0 = __floats2half2_rn(v.x, v.y);
                __half2 h1 = __floats2half2_rn(v.z, v.w);
                *(__half2*)&sB[brow * LDB + bs + j * 4]     = h0;
                *(__half2*)&sB[brow * LDB + bs + j * 4 + 2] = h1;
            }
        }
        __syncthreads();

#pragma unroll
        for (int kk = 0; kk < 4; kk++) {
            wmma::fragment<wmma::matrix_a, 16, 16, 16, __half, wmma::row_major> fa[2];
            wmma::fragment<wmma::matrix_b, 16, 16, 16, __half, wmma::row_major> fb[2];
#pragma unroll
            for (int mi = 0; mi < 2; mi++)
                wmma::load_matrix_sync(fa[mi], &sA[(wm * 32 + mi * 16) * LDA + kk * 16], LDA);
#pragma unroll
            for (int ni = 0; ni < 2; ni++)
                wmma::load_matrix_sync(fb[ni], &sB[kk * 16 * LDB + wn * 32 + ni * 16], LDB);
#pragma unroll
            for (int mi = 0; mi < 2; mi++)
#pragma unroll
                for (int ni = 0; ni < 2; ni++)
                    wmma::mma_sync(acc[mi][ni], fa[mi], fb[ni], acc[mi][ni]);
        }
        __syncthreads();
    }

#pragma unroll
    for (int mi = 0; mi < 2; mi++)
#pragma unroll
        for (int ni = 0; ni < 2; ni++)
            wmma::store_matrix_sync(&sC[(wm * 32 + mi * 16) * F + wn * 32 + ni * 16],
                                    acc[mi][ni], F, wmma::mem_row_major);
    __syncthreads();

    // epilogue: thread t -> (local row = t>>2, channel quarter q = t&3)
    {
        int lrow = tid >> 2;
        int q = tid & 3;
        int grow = row0 + lrow;
        float s1[H], s2[H];
        __half buf[32];
#pragma unroll
        for (int h = 0; h < H; h++) { s1[h] = 0.f; s2[h] = 0.f; }
#pragma unroll
        for (int h = 0; h < H; h++) {
            const float* cr = &sC[lrow * F + h * C + q * 8];
            const float* a1 = &s_att[h * 2 * C + q * 8];
            const float* a2 = a1 + C;
#pragma unroll
            for (int j = 0; j < 8; j++) {
                float v = cr[j];
                s1[h] += v * a1[j];
                s2[h] += v * a2[j];
                buf[j * 4 + h] = __float2half_rn(v);   // interleaved [c][h]
            }
        }
#pragma unroll
        for (int h = 0; h < H; h++) {
            s1[h] += __shfl_xor_sync(0xffffffffu, s1[h], 1);
            s1[h] += __shfl_xor_sync(0xffffffffu, s1[h], 2);
            s2[h] += __shfl_xor_sync(0xffffffffu, s2[h], 1);
            s2[h] += __shfl_xor_sync(0xffffffffu, s2[h], 2);
        }
        if (grow < N) {
            *(uint4*)&g_xwh[grow * F + q * 32]      = *(uint4*)&buf[0];
            *(uint4*)&g_xwh[grow * F + q * 32 + 8]  = *(uint4*)&buf[8];
            *(uint4*)&g_xwh[grow * F + q * 32 + 16] = *(uint4*)&buf[16];
            *(uint4*)&g_xwh[grow * F + q * 32 + 24] = *(uint4*)&buf[24];
            g_ai[grow * H + q] = s1[q];
            g_aj[grow * H + q] = s2[q];
            g_segsum[grow * H + q] = 0.0f;
            float4 b0 = *(const float4*)&bias[q * 8];
            float4 b1 = *(const float4*)&bias[q * 8 + 4];
            *(float4*)&out[grow * C + q * 8]     = b0;
            *(float4*)&out[grow * C + q * 8 + 4] = b1;
        }
    }
}

// ---------------------------------------------------------------------------
// fast exp on the FMA/ALU pipes (no MUFU)
__device__ __forceinline__ float fast_exp(float x) {
    float t = x * 1.4426950408889634f;
    t = fminf(fmaxf(t, -80.0f), 80.0f);
    float fi = floorf(t);
    float f = t - fi;
    float p = 1.3534581508e-2f;
    p = fmaf(p, f, 5.2011464331e-2f);
    p = fmaf(p, f, 2.4144275732e-1f);
    p = fmaf(p, f, 6.9300613463e-1f);
    p = fmaf(p, f, 9.9999989038e-1f);
    return __int_as_float(__float_as_int(p) + ((int)fi << 23));
}
__device__ __forceinline__ float leaky_exp(float a) {
    a = (a >= 0.f) ? a : 0.2f * a;
    return fast_exp(a);
}

// ---------------------------------------------------------------------------
// per-edge: p = exp(leaky(ai[row] + aj[col])); segsum[row] += p (one v4 red).
// PDL: index loads (independent of gemm) issue BEFORE the grid-dependency
// sync, overlapping with gemm's tail; ai/aj reads come after.
__global__ void k_edge1(const int* __restrict__ ei, int E) {
    int e = blockIdx.x * blockDim.x + threadIdx.x;
    if (e >= E) return;
    int r = ei[e];
    int c = ei[E + e];

    cudaGridDependencySynchronize();

    float4 ai = *(const float4*)&g_ai[r * H];
    float4 aj = *(const float4*)&g_aj[c * H];
    float4 p;
    p.x = leaky_exp(ai.x + aj.x);
    p.y = leaky_exp(ai.y + aj.y);
    p.z = leaky_exp(ai.z + aj.z);
    p.w = leaky_exp(ai.w + aj.w);
    *(float4*)&g_p[e * H] = p;
    red_add_v4(&g_segsum[r * H], p.x, p.y, p.z, p.w);
}

// ---------------------------------------------------------------------------
// aggregation: 8 lanes per edge, inline softmax reciprocal, one red.v4/lane.
// PDL: indices AND the g_xwh row (written by gemm, complete once edge1 runs)
// prefetch before the sync; only g_p / g_segsum (edge1 outputs) wait.
__global__ void k_edge2(const int* __restrict__ ei, float* __restrict__ out, int E) {
    int gt = blockIdx.x * blockDim.x + threadIdx.x;
    int e = gt >> 3;
    if (e >= E) return;
    int l = gt & 7;

    int r = __ldg(&ei[e]);
    int c = __ldg(&ei[E + e]);

    // prologue gather: channels 4l..4l+3 -> halfs [16l..16l+15] (32B)
    const __half* xr = &g_xwh[r * F + l * 16];
    uint4 ua = *(const uint4*)&xr[0];
    uint4 ub = *(const uint4*)&xr[8];

    cudaGridDependencySynchronize();

    float4 p = *(const float4*)&g_p[e * H];
    float4 s = *(const float4*)&g_segsum[r * H];
    float w0 = p.x * __fdividef(0.25f, s.x + 1e-16f);
    float w1 = p.y * __fdividef(0.25f, s.y + 1e-16f);
    float w2 = p.z * __fdividef(0.25f, s.z + 1e-16f);
    float w3 = p.w * __fdividef(0.25f, s.w + 1e-16f);

    float2 c0a = __half22float2(*reinterpret_cast<__half2*>(&ua.x));
    float2 c0b = __half22float2(*reinterpret_cast<__half2*>(&ua.y));
    float2 c1a = __half22float2(*reinterpret_cast<__half2*>(&ua.z));
    float2 c1b = __half22float2(*reinterpret_cast<__half2*>(&ua.w));
    float2 c2a = __half22float2(*reinterpret_cast<__half2*>(&ub.x));
    float2 c2b = __half22float2(*reinterpret_cast<__half2*>(&ub.y));
    float2 c3a = __half22float2(*reinterpret_cast<__half2*>(&ub.z));
    float2 c3b = __half22float2(*reinterpret_cast<__half2*>(&ub.w));

    float m0 = w0 * c0a.x + w1 * c0a.y + w2 * c0b.x + w3 * c0b.y;
    float m1 = w0 * c1a.x + w1 * c1a.y + w2 * c1b.x + w3 * c1b.y;
    float m2 = w0 * c2a.x + w1 * c2a.y + w2 * c2b.x + w3 * c2b.y;
    float m3 = w0 * c3a.x + w1 * c3a.y + w2 * c3b.x + w3 * c3b.y;

    red_add_v4(&out[c * C + l * 4], m0, m1, m2, m3);
}

// ---------------------------------------------------------------------------
extern "C" void kernel_launch(void* const* d_in, const int* in_sizes, int n_in,
                              void* d_out, int out_size) {
    const float* x    = (const float*)d_in[0];
    const int*   ei   = (const int*)d_in[1];
    const float* w    = (const float*)d_in[2];
    const float* att  = (const float*)d_in[3];
    const float* bias = (const float*)d_in[4];
    float* out = (float*)d_out;

    int N = in_sizes[0] / F;
    int E = in_sizes[1] / 2;

    k_gemm<<<(N + BM - 1) / BM, 256>>>(x, w, att, bias, out, N);

    cudaLaunchAttribute attr;
    attr.id = cudaLaunchAttributeProgrammaticStreamSerialization;
    attr.val.programmaticStreamSerializationAllowed = 1;

    cudaLaunchConfig_t cfg1 = {};
    cfg1.gridDim = dim3((E + 255) / 256);
    cfg1.blockDim = dim3(256);
    cfg1.stream = 0;
    cfg1.attrs = &attr;
    cfg1.numAttrs = 1;
    cudaLaunchKernelEx(&cfg1, k_edge1, ei, E);

    cudaLaunchConfig_t cfg2 = {};
    cfg2.gridDim = dim3((E * 8 + 255) / 256);
    cfg2.blockDim = dim3(256);
    cfg2.stream = 0;
    cfg2.attrs = &attr;
    cfg2.numAttrs = 1;
    cudaLaunchKernelEx(&cfg2, k_edge2, ei, out, E);
}